// round 12
// baseline (speedup 1.0000x reference)
#include <cuda_runtime.h>
#include <cuda_fp16.h>

// Triplane sampling, GB300 (sm_103a).
// capture stream: transpose s0,s1,s2 -> gather
// side stream:    transpose s3 (fp32->fp16, 339MB); blocks bump g_done3[plane]
// gather: grid (ceil(N*9/256), 3), blockIdx.y = plane. Each block samples
// scales 0-2 for its plane, writes blocks 0-2, waits ONLY for its plane's
// third of the s3 transpose, then samples s3. Planes complete in dispatch
// order (y=0 first), so phase-2 pipelines against the remaining transpose.

#define CDIM 72
#define NCHUNK_H 9            // 72 / 8 halves per uint4 chunk
#define S3_BLOCKS_PER_PLANE 4096

__device__ __half g_tph[75202560];   // 150.4 MB fp16 scratch, channel-major
__device__ int    g_done3[3] = {0, 0, 0};  // s3 transpose blocks done, per plane
__device__ int    g_fin = 0;               // gather blocks done (for reset)

__device__ __forceinline__ unsigned h2_bits(__half2 h) {
    union { __half2 h; unsigned u; } cv;
    cv.h = h;
    return cv.u;
}

// ---------------- transpose: [3,72,r2] fp32 -> [3, r2, 72] fp16 ----------------
__global__ __launch_bounds__(288) void transpose_k(
    const float* __restrict__ in, int off, int r2, int notify)
{
    __shared__ float tile[64 * 77];
    const int p   = blockIdx.y;
    const int t0  = blockIdx.x * 64;
    const int tid = threadIdx.x;

    const float* src = in + (size_t)p * CDIM * r2 + t0;
    #pragma unroll
    for (int i = 0; i < 4; i++) {
        int idx = i * 288 + tid;          // 0..1151
        int c = idx >> 4;                 // channel 0..71
        int v = idx & 15;                 // float4 index over 64 texels
        float4 d = __ldg((const float4*)(src + (size_t)c * r2) + v);
        float* tp = tile + (4 * v) * 77 + c;
        tp[0 * 77] = d.x;
        tp[1 * 77] = d.y;
        tp[2 * 77] = d.z;
        tp[3 * 77] = d.w;
    }
    __syncthreads();

    uint4* dst = (uint4*)(g_tph + off) + ((size_t)p * r2 + t0) * NCHUNK_H;
    #pragma unroll
    for (int i = 0; i < 2; i++) {
        int lin = i * 288 + tid;          // 0..575
        int x = lin / NCHUNK_H;
        int q = lin - x * NCHUNK_H;
        const float* tp = tile + x * 77 + 8 * q;
        uint4 o;
        o.x = h2_bits(__floats2half2_rn(tp[0], tp[1]));
        o.y = h2_bits(__floats2half2_rn(tp[2], tp[3]));
        o.z = h2_bits(__floats2half2_rn(tp[4], tp[5]));
        o.w = h2_bits(__floats2half2_rn(tp[6], tp[7]));
        dst[lin] = o;
    }

    if (notify) {
        __syncthreads();
        if (tid == 0) {
            __threadfence();
            atomicAdd(&g_done3[p], 1);
        }
    }
}

// ---------------- bilinear corner fetch for one scale ----------------
__device__ __forceinline__ void sample_scale(
    int p, int k, float cx, float cy, int r, const __half* __restrict__ base,
    float* acc)
{
    const float rm1 = (float)(r - 1);
    float fx = (cx + 1.0f) * 0.5f * rm1;
    float fy = (cy + 1.0f) * 0.5f * rm1;
    fx = fminf(fmaxf(fx, 0.0f), rm1);
    fy = fminf(fmaxf(fy, 0.0f), rm1);

    const float x0f = floorf(fx);
    const float y0f = floorf(fy);
    const float wx = fx - x0f;
    const float wy = fy - y0f;
    const int x0 = (int)x0f;
    const int y0 = (int)y0f;
    const int x1 = min(x0 + 1, r - 1);
    const int y1 = min(y0 + 1, r - 1);

    const unsigned row0 = (unsigned)(p * r + y0) * (unsigned)r;
    const unsigned row1 = (unsigned)(p * r + y1) * (unsigned)r;

    const uint4 u00 = __ldg((const uint4*)(base + (size_t)(row0 + x0) * CDIM) + k);
    const uint4 u01 = __ldg((const uint4*)(base + (size_t)(row0 + x1) * CDIM) + k);
    const uint4 u10 = __ldg((const uint4*)(base + (size_t)(row1 + x0) * CDIM) + k);
    const uint4 u11 = __ldg((const uint4*)(base + (size_t)(row1 + x1) * CDIM) + k);

    const float w00 = (1.0f - wx) * (1.0f - wy);
    const float w01 = wx * (1.0f - wy);
    const float w10 = (1.0f - wx) * wy;
    const float w11 = wx * wy;

    #pragma unroll
    for (int h = 0; h < 4; h++) {
        const unsigned a00 = (&u00.x)[h], a01 = (&u01.x)[h];
        const unsigned a10 = (&u10.x)[h], a11 = (&u11.x)[h];
        float2 f00 = __half22float2(*(const __half2*)&a00);
        float2 f01 = __half22float2(*(const __half2*)&a01);
        float2 f10 = __half22float2(*(const __half2*)&a10);
        float2 f11 = __half22float2(*(const __half2*)&a11);
        acc[2*h+0] += f00.x * w00 + f01.x * w01 + f10.x * w10 + f11.x * w11;
        acc[2*h+1] += f00.y * w00 + f01.y * w01 + f10.y * w10 + f11.y * w11;
    }
}

// ---------------- gather: blockIdx.y = plane; per-plane s3 wait ----------------
__global__ __launch_bounds__(256) void gather_k(
    const float* __restrict__ pts, float* __restrict__ out, int N)
{
    const int p   = blockIdx.y;
    const int gid = blockIdx.x * blockDim.x + threadIdx.x;  // over n*9 + k
    const int total = N * NCHUNK_H;
    const bool valid = (gid < total);

    int k = 0;
    float cx = 0.f, cy = 0.f;
    float* outrow = out;
    float acc[8];
    #pragma unroll
    for (int i = 0; i < 8; i++) acc[i] = 0.0f;

    if (valid) {
        const int n = gid / NCHUNK_H;
        k = gid - n * NCHUNK_H;

        const float d0 = -0.625f * __ldg(&pts[3 * n + 0]);
        const float d1 = -0.625f * __ldg(&pts[3 * n + 1]);
        const float d2 = -0.625f * __ldg(&pts[3 * n + 2]);
        cx = (p == 2) ? d1 : d0;
        cy = (p == 0) ? d1 : d2;

        outrow = out + (size_t)n * 864 + p * CDIM + k * 8;

        // scales 0-2 (small transposes completed earlier on this stream)
        const int resos[3] = {64, 128, 256};
        const int offs[3]  = {0, 884736, 4423680};
        #pragma unroll
        for (int s = 0; s < 3; s++) {
            sample_scale(p, k, cx, cy, resos[s], g_tph + offs[s], acc);
            __stcs((float4*)(outrow + s * 216),
                   make_float4(acc[0], acc[1], acc[2], acc[3]));
            __stcs((float4*)(outrow + s * 216) + 1,
                   make_float4(acc[4], acc[5], acc[6], acc[7]));
        }
    }

    // wait only for THIS plane's third of the s3 transpose
    if (threadIdx.x == 0) {
        while (atomicAdd(&g_done3[p], 0) < S3_BLOCKS_PER_PLANE) __nanosleep(128);
        __threadfence();
    }
    __syncthreads();

    if (valid) {
        sample_scale(p, k, cx, cy, 512, g_tph + 18579456, acc);
        __stcs((float4*)(outrow + 3 * 216),
               make_float4(acc[0], acc[1], acc[2], acc[3]));
        __stcs((float4*)(outrow + 3 * 216) + 1,
               make_float4(acc[4], acc[5], acc[6], acc[7]));
    }

    // replay-safe reset: last gather block zeroes all counters
    __syncthreads();
    if (threadIdx.x == 0) {
        int nblocks = (int)(gridDim.x * gridDim.y);
        int f = atomicAdd(&g_fin, 1);
        if (f == nblocks - 1) {
            atomicExch(&g_done3[0], 0);
            atomicExch(&g_done3[1], 0);
            atomicExch(&g_done3[2], 0);
            atomicExch(&g_fin, 0);
        }
    }
}

extern "C" void kernel_launch(void* const* d_in, const int* in_sizes, int n_in,
                              void* d_out, int out_size)
{
    const float* pts = (const float*)d_in[0];
    const int N = in_sizes[0] / 3;
    float* out = (float*)d_out;

    static const int res[4]  = {64, 128, 256, 512};
    static const int offs[4] = {0, 884736, 4423680, 18579456};

    static cudaStream_t s_side = nullptr;
    static cudaEvent_t  s_ev_fork = nullptr, s_ev_join = nullptr;
    static bool s_init = false;
    if (!s_init) {
        s_init = true;
        if (cudaStreamCreateWithFlags(&s_side, cudaStreamNonBlocking) != cudaSuccess)
            s_side = nullptr;
        cudaEventCreateWithFlags(&s_ev_fork, cudaEventDisableTiming);
        cudaEventCreateWithFlags(&s_ev_join, cudaEventDisableTiming);
    }
    const bool fork = (s_side != nullptr && s_ev_fork && s_ev_join);
    cudaStream_t sb = fork ? s_side : (cudaStream_t)0;

    if (fork) {
        cudaEventRecord(s_ev_fork, 0);
        cudaStreamWaitEvent(sb, s_ev_fork, 0);
    }

    // Side stream: the big s3 transpose; plane y blocks bump g_done3[y].
    {
        const float* g = (const float*)d_in[4];
        const int r2 = 512 * 512;
        dim3 grid(r2 / 64, 3);
        transpose_k<<<grid, 288, 0, sb>>>(g, offs[3], r2, 1);
    }

    // Capture stream: small transposes, then plane-split gather.
    for (int s = 0; s < 3; s++) {
        const float* g = (const float*)d_in[1 + s];
        const int r2 = res[s] * res[s];
        dim3 grid(r2 / 64, 3);
        transpose_k<<<grid, 288>>>(g, offs[s], r2, 0);
    }
    {
        const int per_plane = N * NCHUNK_H;
        dim3 grid((per_plane + 255) / 256, 3);
        gather_k<<<grid, 256>>>(pts, out, N);
    }

    // Join side stream after gather (capture validity; no added dependency).
    if (fork) {
        cudaEventRecord(s_ev_join, sb);
        cudaStreamWaitEvent(0, s_ev_join, 0);
    }
}

// round 15
// speedup vs baseline: 1.0100x; 1.0100x over previous
#include <cuda_runtime.h>
#include <cuda_fp16.h>

// Triplane sampling, GB300 (sm_103a).
// capture stream: transpose s0,s1,s2 -> gather (samples s0-2, writes blocks
//                 0-2, flag-waits for s3 transpose, samples s3)
// side stream:    transpose s3 (fp32->fp16, 339MB); blocks bump g_done
// fp16 channel-major scratch [scale][plane][texel][72]; transpose converts
// to fp16 BEFORE smem (uint = half2 channel-pair), STS.128/LDS.32/STG.128.

#define CDIM 72
#define NCHUNK_H 9           // 72 / 8 halves per uint4 chunk
#define THREADS_PER_PT 27    // 3 planes * 9 chunks
#define S3_BLOCKS (4096 * 3) // s3 transpose grid (r2/64, 3)

__device__ __half g_tph[75202560];   // 150.4 MB fp16 scratch, channel-major
__device__ int    g_done = 0;        // s3 transpose blocks completed
__device__ int    g_fin  = 0;        // gather blocks completed (for reset)

__device__ __forceinline__ unsigned h2_bits(__half2 h) {
    union { __half2 h; unsigned u; } cv;
    cv.h = h;
    return cv.u;
}

// ---------------- transpose: [3,72,r2] fp32 -> [3, r2, 72] fp16 ----------------
// Block = one plane x 64 texels x 72 channels, 288 threads.
// Phase A: thread loads channels (2cp, 2cp+1) for texel-quad v (2x LDG.128),
//          packs 4x half2, one STS.128 into tile[cp][4v..4v+3].
// Phase B: output uint4 = channel-pairs 4q..4q+3 of texel x: 4x LDS.32 + STG.128.
__global__ __launch_bounds__(288) void transpose_k(
    const float* __restrict__ in, int off, int r2, int notify)
{
    __shared__ unsigned tile[36 * 68];   // [ch-pair][texel], row pad 68
    const int p   = blockIdx.y;
    const int t0  = blockIdx.x * 64;
    const int tid = threadIdx.x;

    const float* src = in + (size_t)p * CDIM * r2 + t0;
    #pragma unroll
    for (int i = 0; i < 2; i++) {
        int idx = i * 288 + tid;         // 0..575
        int v   = idx & 15;              // texel quad 0..15
        int cp  = idx >> 4;              // channel pair 0..35
        const float* sp = src + (size_t)(2 * cp) * r2 + 4 * v;
        float4 a = __ldg((const float4*)sp);
        float4 b = __ldg((const float4*)(sp + r2));
        uint4 o;
        o.x = h2_bits(__floats2half2_rn(a.x, b.x));
        o.y = h2_bits(__floats2half2_rn(a.y, b.y));
        o.z = h2_bits(__floats2half2_rn(a.z, b.z));
        o.w = h2_bits(__floats2half2_rn(a.w, b.w));
        *(uint4*)&tile[cp * 68 + 4 * v] = o;
    }
    __syncthreads();

    uint4* dst = (uint4*)(g_tph + off) + ((size_t)p * r2 + t0) * NCHUNK_H;
    #pragma unroll
    for (int i = 0; i < 2; i++) {
        int lin = i * 288 + tid;         // 0..575
        int x = lin / NCHUNK_H;          // texel 0..63
        int q = lin - x * NCHUNK_H;      // uint4 index 0..8
        uint4 o;
        o.x = tile[(4 * q + 0) * 68 + x];
        o.y = tile[(4 * q + 1) * 68 + x];
        o.z = tile[(4 * q + 2) * 68 + x];
        o.w = tile[(4 * q + 3) * 68 + x];
        dst[lin] = o;
    }

    if (notify) {
        __syncthreads();
        if (tid == 0) {
            __threadfence();
            atomicAdd(&g_done, 1);
        }
    }
}

// ---------------- bilinear corner fetch for one scale ----------------
__device__ __forceinline__ void sample_scale(
    int p, int k, float cx, float cy, int r, const __half* __restrict__ base,
    float* acc)
{
    const float rm1 = (float)(r - 1);
    float fx = (cx + 1.0f) * 0.5f * rm1;
    float fy = (cy + 1.0f) * 0.5f * rm1;
    fx = fminf(fmaxf(fx, 0.0f), rm1);
    fy = fminf(fmaxf(fy, 0.0f), rm1);

    const float x0f = floorf(fx);
    const float y0f = floorf(fy);
    const float wx = fx - x0f;
    const float wy = fy - y0f;
    const int x0 = (int)x0f;
    const int y0 = (int)y0f;
    const int x1 = min(x0 + 1, r - 1);
    const int y1 = min(y0 + 1, r - 1);

    const unsigned row0 = (unsigned)(p * r + y0) * (unsigned)r;
    const unsigned row1 = (unsigned)(p * r + y1) * (unsigned)r;

    const uint4 u00 = __ldg((const uint4*)(base + (size_t)(row0 + x0) * CDIM) + k);
    const uint4 u01 = __ldg((const uint4*)(base + (size_t)(row0 + x1) * CDIM) + k);
    const uint4 u10 = __ldg((const uint4*)(base + (size_t)(row1 + x0) * CDIM) + k);
    const uint4 u11 = __ldg((const uint4*)(base + (size_t)(row1 + x1) * CDIM) + k);

    const float w00 = (1.0f - wx) * (1.0f - wy);
    const float w01 = wx * (1.0f - wy);
    const float w10 = (1.0f - wx) * wy;
    const float w11 = wx * wy;

    #pragma unroll
    for (int h = 0; h < 4; h++) {
        const unsigned a00 = (&u00.x)[h], a01 = (&u01.x)[h];
        const unsigned a10 = (&u10.x)[h], a11 = (&u11.x)[h];
        float2 f00 = __half22float2(*(const __half2*)&a00);
        float2 f01 = __half22float2(*(const __half2*)&a01);
        float2 f10 = __half22float2(*(const __half2*)&a10);
        float2 f11 = __half22float2(*(const __half2*)&a11);
        acc[2*h+0] += f00.x * w00 + f01.x * w01 + f10.x * w10 + f11.x * w11;
        acc[2*h+1] += f00.y * w00 + f01.y * w01 + f10.y * w10 + f11.y * w11;
    }
}

// ---------------- gather (original point order; flag-fused with s3 transpose) --
__global__ __launch_bounds__(256) void gather_k(
    const float* __restrict__ pts, float* __restrict__ out, int N)
{
    const int gid = blockIdx.x * blockDim.x + threadIdx.x;
    const int total = N * THREADS_PER_PT;
    const bool valid = (gid < total);

    int p = 0, k = 0;
    float cx = 0.f, cy = 0.f;
    float* outrow = out;
    float acc[8];
    #pragma unroll
    for (int i = 0; i < 8; i++) acc[i] = 0.0f;

    if (valid) {
        const int n = gid / THREADS_PER_PT;
        const int j = gid - n * THREADS_PER_PT;
        p = j / NCHUNK_H;
        k = j - p * NCHUNK_H;

        const float d0 = -0.625f * __ldg(&pts[3 * n + 0]);
        const float d1 = -0.625f * __ldg(&pts[3 * n + 1]);
        const float d2 = -0.625f * __ldg(&pts[3 * n + 2]);
        cx = (p == 2) ? d1 : d0;
        cy = (p == 0) ? d1 : d2;

        outrow = out + (size_t)n * 864 + p * CDIM + k * 8;

        const int resos[3] = {64, 128, 256};
        const int offs[3]  = {0, 884736, 4423680};
        #pragma unroll
        for (int s = 0; s < 3; s++) {
            sample_scale(p, k, cx, cy, resos[s], g_tph + offs[s], acc);
            __stcs((float4*)(outrow + s * 216),
                   make_float4(acc[0], acc[1], acc[2], acc[3]));
            __stcs((float4*)(outrow + s * 216) + 1,
                   make_float4(acc[4], acc[5], acc[6], acc[7]));
        }
    }

    // wait for the s3 transpose (runs concurrently on the side stream)
    if (threadIdx.x == 0) {
        while (atomicAdd(&g_done, 0) < S3_BLOCKS) __nanosleep(128);
        __threadfence();
    }
    __syncthreads();

    if (valid) {
        sample_scale(p, k, cx, cy, 512, g_tph + 18579456, acc);
        __stcs((float4*)(outrow + 3 * 216),
               make_float4(acc[0], acc[1], acc[2], acc[3]));
        __stcs((float4*)(outrow + 3 * 216) + 1,
               make_float4(acc[4], acc[5], acc[6], acc[7]));
    }

    // replay-safe reset: last gather block zeroes the counters
    __syncthreads();
    if (threadIdx.x == 0) {
        int f = atomicAdd(&g_fin, 1);
        if (f == (int)gridDim.x - 1) {
            atomicExch(&g_done, 0);
            atomicExch(&g_fin, 0);
        }
    }
}

extern "C" void kernel_launch(void* const* d_in, const int* in_sizes, int n_in,
                              void* d_out, int out_size)
{
    const float* pts = (const float*)d_in[0];
    const int N = in_sizes[0] / 3;
    float* out = (float*)d_out;

    static const int res[4]  = {64, 128, 256, 512};
    static const int offs[4] = {0, 884736, 4423680, 18579456};

    static cudaStream_t s_side = nullptr;
    static cudaEvent_t  s_ev_fork = nullptr, s_ev_join = nullptr;
    static bool s_init = false;
    if (!s_init) {
        s_init = true;
        if (cudaStreamCreateWithFlags(&s_side, cudaStreamNonBlocking) != cudaSuccess)
            s_side = nullptr;
        cudaEventCreateWithFlags(&s_ev_fork, cudaEventDisableTiming);
        cudaEventCreateWithFlags(&s_ev_join, cudaEventDisableTiming);
    }
    const bool fork = (s_side != nullptr && s_ev_fork && s_ev_join);
    cudaStream_t sb = fork ? s_side : (cudaStream_t)0;

    if (fork) {
        cudaEventRecord(s_ev_fork, 0);
        cudaStreamWaitEvent(sb, s_ev_fork, 0);
    }

    // Side stream: the big s3 transpose; blocks bump g_done as they finish.
    {
        const float* g = (const float*)d_in[4];
        const int r2 = 512 * 512;
        dim3 grid(r2 / 64, 3);
        transpose_k<<<grid, 288, 0, sb>>>(g, offs[3], r2, 1);
    }

    // Capture stream: small transposes, then gather (flag-waits for s3 inside).
    for (int s = 0; s < 3; s++) {
        const float* g = (const float*)d_in[1 + s];
        const int r2 = res[s] * res[s];
        dim3 grid(r2 / 64, 3);
        transpose_k<<<grid, 288>>>(g, offs[s], r2, 0);
    }
    const int total = N * THREADS_PER_PT;
    gather_k<<<(total + 255) / 256, 256>>>(pts, out, N);

    // Join side stream after gather (capture validity; no added dependency).
    if (fork) {
        cudaEventRecord(s_ev_join, sb);
        cudaStreamWaitEvent(0, s_ev_join, 0);
    }
}